// round 3
// baseline (speedup 1.0000x reference)
#include <cuda_runtime.h>
#include <cstdint>
#include <cfloat>

#define NN 40000
#define EE 640000
#define GG 64
#define DD 128
#define HH 128
#define OO 10
#define NPW 8   // nodes per warp in k_agg

typedef unsigned long long ull;

// ---------------- scratch (static device globals; no allocations) ----------------
__device__ float    g_h[NN * HH];      // x @ W_gcn (L2-resident, 20.5 MB)
__device__ int      g_degi[NN];
__device__ float    g_dinv[NN];
__device__ int      g_off[NN + 1];     // CSR row offsets (by dst)
__device__ int      g_cursor[NN];
__device__ int2     g_edge[EE];        // CSR: (src, bits(dinv[src])) per edge slot
__device__ float    g_addpool[GG * HH];
__device__ unsigned g_maxpool[GG * HH];
__device__ int      g_counts[GG];

// order-preserving float <-> unsigned encoding for atomicMax
__device__ __forceinline__ unsigned fkey(float f) {
    int i = __float_as_int(f);
    return (unsigned)(i ^ ((i >> 31) | 0x80000000));
}
__device__ __forceinline__ float fdec(unsigned k) {
    int i = (k & 0x80000000u) ? (int)(k ^ 0x80000000u) : (int)(~k);
    return __int_as_float(i);
}

// packed f32x2 helpers (PTX-only; ptxas never emits FFMA2 from C++)
__device__ __forceinline__ ull pk2(float lo, float hi) {
    ull r; asm("mov.b64 %0, {%1, %2};" : "=l"(r) : "f"(lo), "f"(hi)); return r;
}
__device__ __forceinline__ void upk2(ull v, float& lo, float& hi) {
    asm("mov.b64 {%0, %1}, %2;" : "=f"(lo), "=f"(hi) : "l"(v));
}
__device__ __forceinline__ ull ffma2(ull a, ull b, ull c) {
    ull d; asm("fma.rn.f32x2 %0, %1, %2, %3;" : "=l"(d) : "l"(a), "l"(b), "l"(c));
    return d;
}

// ---------------- kernels ----------------
__global__ void k_init() {
    int i = blockIdx.x * blockDim.x + threadIdx.x;
    if (i < NN)      g_degi[i] = 0;
    if (i < GG * HH) { g_addpool[i] = 0.f; g_maxpool[i] = 0u; }
    if (i < GG)      g_counts[i] = 0;
}

__global__ void k_deg(const int* __restrict__ ei) {
    int e = blockIdx.x * blockDim.x + threadIdx.x;
    if (e >= EE) return;
    atomicAdd(&g_degi[ei[EE + e]], 1);
}

// Single-block scan over 40000 degree counts -> CSR offsets + cursors + dinv.
__global__ void k_scan() {
    __shared__ int s_sum[1024];
    const int CH = (NN + 1023) / 1024;     // 40
    int t = threadIdx.x;
    int base = t * CH;
    int s = 0;
#pragma unroll 8
    for (int i = 0; i < CH; i++) {
        int idx = base + i;
        if (idx < NN) s += g_degi[idx];
    }
    s_sum[t] = s;
    __syncthreads();
    for (int o = 1; o < 1024; o <<= 1) {
        int v = (t >= o) ? s_sum[t - o] : 0;
        __syncthreads();
        s_sum[t] += v;
        __syncthreads();
    }
    int run = (t > 0) ? s_sum[t - 1] : 0;
    for (int i = 0; i < CH; i++) {
        int idx = base + i;
        if (idx < NN) {
            int d = g_degi[idx];
            g_off[idx] = run;
            g_cursor[idx] = run;
            run += d;
            g_dinv[idx] = rsqrtf((float)d + 1.0f);
        }
    }
    if (t == (NN - 1) / CH) g_off[NN] = run;
}

__global__ void k_place(const int* __restrict__ ei) {
    int e = blockIdx.x * blockDim.x + threadIdx.x;
    if (e >= EE) return;
    int src = ei[e];
    int dst = ei[EE + e];
    int pos = atomicAdd(&g_cursor[dst], 1);
    g_edge[pos] = make_int2(src, __float_as_int(g_dinv[src]));
}

// h = x @ W. 64x128 tile, 256 threads, packed f32x2 FFMA (row-pair accumulators).
__global__ void k_gemm(const float* __restrict__ x, const float* __restrict__ W) {
    extern __shared__ float sm[];
    float* Ws = sm;                 // 128*128
    float* Xs = sm + DD * HH;       // 16 * 72 (transposed x tile)
    const int XLD = 72;
    int tid = threadIdx.x;
    int row0 = blockIdx.x * 64;

    for (int i = tid; i < (DD * HH) / 4; i += 256)
        ((float4*)Ws)[i] = ((const float4*)W)[i];

    int tx = tid & 31;              // cols tx*4 .. tx*4+3
    int ty = tid >> 5;              // rows ty*8 .. ty*8+7 (as 4 pairs)
    ull acc[4][4];                  // [row-pair][col]
#pragma unroll
    for (int rp = 0; rp < 4; rp++)
#pragma unroll
        for (int c = 0; c < 4; c++) acc[rp][c] = 0ULL;

    int lr = tid >> 2, lk = tid & 3;
    for (int kt = 0; kt < DD; kt += 16) {
        __syncthreads();
        float4 xv = *(const float4*)(x + (size_t)(row0 + lr) * DD + kt + lk * 4);
        Xs[(lk * 4 + 0) * XLD + lr] = xv.x;
        Xs[(lk * 4 + 1) * XLD + lr] = xv.y;
        Xs[(lk * 4 + 2) * XLD + lr] = xv.z;
        Xs[(lk * 4 + 3) * XLD + lr] = xv.w;
        __syncthreads();
#pragma unroll
        for (int kk = 0; kk < 16; kk++) {
            float4 wv = *(const float4*)(Ws + (kt + kk) * HH + tx * 4);
            ulonglong2 xa = *(const ulonglong2*)(Xs + kk * XLD + ty * 8);
            ulonglong2 xb = *(const ulonglong2*)(Xs + kk * XLD + ty * 8 + 4);
            ull xp[4] = {xa.x, xa.y, xb.x, xb.y};
            ull w0 = pk2(wv.x, wv.x), w1 = pk2(wv.y, wv.y);
            ull w2 = pk2(wv.z, wv.z), w3 = pk2(wv.w, wv.w);
#pragma unroll
            for (int rp = 0; rp < 4; rp++) {
                acc[rp][0] = ffma2(xp[rp], w0, acc[rp][0]);
                acc[rp][1] = ffma2(xp[rp], w1, acc[rp][1]);
                acc[rp][2] = ffma2(xp[rp], w2, acc[rp][2]);
                acc[rp][3] = ffma2(xp[rp], w3, acc[rp][3]);
            }
        }
    }
#pragma unroll
    for (int rp = 0; rp < 4; rp++) {
        float l0, h0, l1, h1, l2, h2, l3, h3;
        upk2(acc[rp][0], l0, h0);
        upk2(acc[rp][1], l1, h1);
        upk2(acc[rp][2], l2, h2);
        upk2(acc[rp][3], l3, h3);
        size_t r = (size_t)(row0 + ty * 8 + 2 * rp) * HH + tx * 4;
        *(float4*)(g_h + r)      = make_float4(l0, l1, l2, l3);
        *(float4*)(g_h + r + HH) = make_float4(h0, h1, h2, h3);
    }
}

__device__ __forceinline__ void pool_flush(int g, int f, float4 padd, float4 pmax,
                                           int pcnt, int lane) {
    float* p = g_addpool + g * HH + f;
    asm volatile("red.global.add.v4.f32 [%0], {%1, %2, %3, %4};"
                 :: "l"(p), "f"(padd.x), "f"(padd.y), "f"(padd.z), "f"(padd.w)
                 : "memory");
    unsigned* mp = g_maxpool + g * HH + f;
    atomicMax(mp + 0, fkey(pmax.x));
    atomicMax(mp + 1, fkey(pmax.y));
    atomicMax(mp + 2, fkey(pmax.z));
    atomicMax(mp + 3, fkey(pmax.w));
    if (lane == 0) atomicAdd(&g_counts[g], pcnt);
}

// One warp per NPW consecutive nodes: CSR gather-reduce (MLP=8 pipelined) +
// self loop + bias + ReLU + LayerNorm + register-privatized pooling.
__global__ void __launch_bounds__(256) k_agg(const int* __restrict__ batch,
                                             const float* __restrict__ bgcn,
                                             const float* __restrict__ gamma,
                                             const float* __restrict__ beta) {
    int warp = blockIdx.x * 8 + (threadIdx.x >> 5);
    int n0 = warp * NPW;
    if (n0 >= NN) return;
    int lane = threadIdx.x & 31;
    int f = lane * 4;

    float4 bb = *(const float4*)(bgcn + f);
    float4 ga = *(const float4*)(gamma + f);
    float4 be = *(const float4*)(beta + f);

    float4 padd = make_float4(0.f, 0.f, 0.f, 0.f);
    float4 pmax = make_float4(-FLT_MAX, -FLT_MAX, -FLT_MAX, -FLT_MAX);
    int pcnt = 0;
    int curg = __ldg(&batch[n0]);

#pragma unroll 1
    for (int k = 0; k < NPW; k++) {
        int n = n0 + k;
        int g = __ldg(&batch[n]);
        if (g != curg) {
            pool_flush(curg, f, padd, pmax, pcnt, lane);
            padd = make_float4(0.f, 0.f, 0.f, 0.f);
            pmax = make_float4(-FLT_MAX, -FLT_MAX, -FLT_MAX, -FLT_MAX);
            pcnt = 0;
            curg = g;
        }
        int s = __ldg(&g_off[n]);
        int e = __ldg(&g_off[n + 1]);
        float4 a0 = make_float4(0.f, 0.f, 0.f, 0.f);
        float4 a1 = make_float4(0.f, 0.f, 0.f, 0.f);
        int j = s;
        if ((j & 1) && j < e) {             // align to int4 boundary
            int2 p = __ldg(&g_edge[j]);
            float c = __int_as_float(p.y);
            const float4 v = *(const float4*)(g_h + (size_t)p.x * HH + f);
            a0.x = fmaf(c, v.x, a0.x); a0.y = fmaf(c, v.y, a0.y);
            a0.z = fmaf(c, v.z, a0.z); a0.w = fmaf(c, v.w, a0.w);
            j++;
        }
        for (; j + 8 <= e; j += 8) {        // 8 gathers in flight
            int4 q0 = *(const int4*)(g_edge + j);
            int4 q1 = *(const int4*)(g_edge + j + 2);
            int4 q2 = *(const int4*)(g_edge + j + 4);
            int4 q3 = *(const int4*)(g_edge + j + 6);
            float4 v0 = *(const float4*)(g_h + (size_t)q0.x * HH + f);
            float4 v1 = *(const float4*)(g_h + (size_t)q0.z * HH + f);
            float4 v2 = *(const float4*)(g_h + (size_t)q1.x * HH + f);
            float4 v3 = *(const float4*)(g_h + (size_t)q1.z * HH + f);
            float4 v4 = *(const float4*)(g_h + (size_t)q2.x * HH + f);
            float4 v5 = *(const float4*)(g_h + (size_t)q2.z * HH + f);
            float4 v6 = *(const float4*)(g_h + (size_t)q3.x * HH + f);
            float4 v7 = *(const float4*)(g_h + (size_t)q3.z * HH + f);
            float c0 = __int_as_float(q0.y), c1 = __int_as_float(q0.w);
            float c2 = __int_as_float(q1.y), c3 = __int_as_float(q1.w);
            float c4 = __int_as_float(q2.y), c5 = __int_as_float(q2.w);
            float c6 = __int_as_float(q3.y), c7 = __int_as_float(q3.w);
            a0.x = fmaf(c0, v0.x, a0.x); a0.y = fmaf(c0, v0.y, a0.y);
            a0.z = fmaf(c0, v0.z, a0.z); a0.w = fmaf(c0, v0.w, a0.w);
            a1.x = fmaf(c1, v1.x, a1.x); a1.y = fmaf(c1, v1.y, a1.y);
            a1.z = fmaf(c1, v1.z, a1.z); a1.w = fmaf(c1, v1.w, a1.w);
            a0.x = fmaf(c2, v2.x, a0.x); a0.y = fmaf(c2, v2.y, a0.y);
            a0.z = fmaf(c2, v2.z, a0.z); a0.w = fmaf(c2, v2.w, a0.w);
            a1.x = fmaf(c3, v3.x, a1.x); a1.y = fmaf(c3, v3.y, a1.y);
            a1.z = fmaf(c3, v3.z, a1.z); a1.w = fmaf(c3, v3.w, a1.w);
            a0.x = fmaf(c4, v4.x, a0.x); a0.y = fmaf(c4, v4.y, a0.y);
            a0.z = fmaf(c4, v4.z, a0.z); a0.w = fmaf(c4, v4.w, a0.w);
            a1.x = fmaf(c5, v5.x, a1.x); a1.y = fmaf(c5, v5.y, a1.y);
            a1.z = fmaf(c5, v5.z, a1.z); a1.w = fmaf(c5, v5.w, a1.w);
            a0.x = fmaf(c6, v6.x, a0.x); a0.y = fmaf(c6, v6.y, a0.y);
            a0.z = fmaf(c6, v6.z, a0.z); a0.w = fmaf(c6, v6.w, a0.w);
            a1.x = fmaf(c7, v7.x, a1.x); a1.y = fmaf(c7, v7.y, a1.y);
            a1.z = fmaf(c7, v7.z, a1.z); a1.w = fmaf(c7, v7.w, a1.w);
        }
        for (; j < e; j++) {                // tail
            int2 p = __ldg(&g_edge[j]);
            float c = __int_as_float(p.y);
            const float4 v = *(const float4*)(g_h + (size_t)p.x * HH + f);
            a0.x = fmaf(c, v.x, a0.x); a0.y = fmaf(c, v.y, a0.y);
            a0.z = fmaf(c, v.z, a0.z); a0.w = fmaf(c, v.w, a0.w);
        }
        float4 acc = make_float4(a0.x + a1.x, a0.y + a1.y, a0.z + a1.z, a0.w + a1.w);

        float di = g_dinv[n];
        float4 hv = *(const float4*)(g_h + (size_t)n * HH + f);
        float4 v;
        v.x = fmaxf(fmaf(fmaf(hv.x, di, acc.x), di, bb.x), 0.f);
        v.y = fmaxf(fmaf(fmaf(hv.y, di, acc.y), di, bb.y), 0.f);
        v.z = fmaxf(fmaf(fmaf(hv.z, di, acc.z), di, bb.z), 0.f);
        v.w = fmaxf(fmaf(fmaf(hv.w, di, acc.w), di, bb.w), 0.f);

        float ssum = v.x + v.y + v.z + v.w;
        float qsum = v.x * v.x + v.y * v.y + v.z * v.z + v.w * v.w;
#pragma unroll
        for (int o = 16; o; o >>= 1) {
            ssum += __shfl_xor_sync(0xffffffffu, ssum, o);
            qsum += __shfl_xor_sync(0xffffffffu, qsum, o);
        }
        float mean = ssum * (1.f / 128.f);
        float var  = qsum * (1.f / 128.f) - mean * mean;
        float rstd = rsqrtf(var + 1e-5f);

        float4 y;
        y.x = fmaf((v.x - mean) * rstd, ga.x, be.x);
        y.y = fmaf((v.y - mean) * rstd, ga.y, be.y);
        y.z = fmaf((v.z - mean) * rstd, ga.z, be.z);
        y.w = fmaf((v.w - mean) * rstd, ga.w, be.w);

        padd.x += y.x; padd.y += y.y; padd.z += y.z; padd.w += y.w;
        pmax.x = fmaxf(pmax.x, y.x); pmax.y = fmaxf(pmax.y, y.y);
        pmax.z = fmaxf(pmax.z, y.z); pmax.w = fmaxf(pmax.w, y.w);
        pcnt++;
    }
    pool_flush(curg, f, padd, pmax, pcnt, lane);
}

// One block per graph: build [mean|add|max] then 384->128->64->10 MLP.
__global__ void k_final(const float* __restrict__ W1, const float* __restrict__ b1,
                        const float* __restrict__ W2, const float* __restrict__ b2,
                        const float* __restrict__ W3, const float* __restrict__ b3,
                        float* __restrict__ out) {
    __shared__ float gv[3 * HH];
    __shared__ float l1[HH];
    __shared__ float l2[HH / 2];
    int g = blockIdx.x;
    int t = threadIdx.x;  // 128

    int cnt = g_counts[g];
    float ad = g_addpool[g * HH + t];
    float mean = ad / fmaxf((float)cnt, 1.f);
    float mx = (cnt > 0) ? fdec(g_maxpool[g * HH + t]) : 0.f;
    gv[t] = mean;
    gv[HH + t] = ad;
    gv[2 * HH + t] = mx;
    __syncthreads();

    float acc = __ldg(&b1[t]);
    for (int k = 0; k < 3 * HH; k++)
        acc = fmaf(gv[k], __ldg(&W1[k * HH + t]), acc);
    l1[t] = fmaxf(acc, 0.f);
    __syncthreads();

    if (t < HH / 2) {
        float a2 = __ldg(&b2[t]);
        for (int k = 0; k < HH; k++)
            a2 = fmaf(l1[k], __ldg(&W2[k * (HH / 2) + t]), a2);
        l2[t] = fmaxf(a2, 0.f);
    }
    __syncthreads();

    if (t < OO) {
        float a3 = __ldg(&b3[t]);
        for (int k = 0; k < HH / 2; k++)
            a3 = fmaf(l2[k], __ldg(&W3[k * OO + t]), a3);
        out[g * OO + t] = a3;
    }
}

// ---------------- launch ----------------
extern "C" void kernel_launch(void* const* d_in, const int* in_sizes, int n_in,
                              void* d_out, int out_size) {
    const float* x     = (const float*)d_in[0];
    const int*   ei    = (const int*)d_in[1];
    const int*   batch = (const int*)d_in[2];
    int idx = 3;
    if (n_in > 3 && in_sizes[3] == 1) idx = 4;
    const float* Wg    = (const float*)d_in[idx++];
    const float* bg    = (const float*)d_in[idx++];
    const float* gamma = (const float*)d_in[idx++];
    const float* beta  = (const float*)d_in[idx++];
    const float* W1    = (const float*)d_in[idx++];
    const float* b1    = (const float*)d_in[idx++];
    const float* W2    = (const float*)d_in[idx++];
    const float* b2    = (const float*)d_in[idx++];
    const float* W3    = (const float*)d_in[idx++];
    const float* b3    = (const float*)d_in[idx++];
    float* out = (float*)d_out;

    static cudaStream_t s2 = nullptr;
    static cudaEvent_t ev1 = nullptr, ev2 = nullptr;
    if (!s2) {
        cudaStreamCreateWithFlags(&s2, cudaStreamNonBlocking);
        cudaEventCreateWithFlags(&ev1, cudaEventDisableTiming);
        cudaEventCreateWithFlags(&ev2, cudaEventDisableTiming);
    }

    const int smem = (DD * HH + 16 * 72) * (int)sizeof(float);
    cudaFuncSetAttribute(k_gemm, cudaFuncAttributeMaxDynamicSharedMemorySize, smem);

    // fork: gemm (x,W only) runs concurrent with CSR build
    cudaEventRecord(ev1, 0);
    cudaStreamWaitEvent(s2, ev1, 0);
    k_gemm<<<NN / 64, 256, smem, s2>>>(x, Wg);
    cudaEventRecord(ev2, s2);

    k_init<<<(NN + 255) / 256, 256>>>();
    k_deg<<<(EE + 255) / 256, 256>>>(ei);
    k_scan<<<1, 1024>>>();
    k_place<<<(EE + 255) / 256, 256>>>(ei);

    cudaStreamWaitEvent(0, ev2, 0);   // join
    k_agg<<<NN / (NPW * 8), 256>>>(batch, bg, gamma, beta);
    k_final<<<GG, 128>>>(W1, b1, W2, b2, W3, b3, out);
}

// round 4
// speedup vs baseline: 1.8516x; 1.8516x over previous
#include <cuda_runtime.h>
#include <cstdint>
#include <cfloat>

#define NN 40000
#define EE 640000
#define GG 64
#define DD 128
#define HH 128
#define OO 10
#define NPW 8            // nodes per warp in k_agg
#define SBLK 157         // scan blocks: ceil(40000/256)

// ---------------- scratch (static device globals; no allocations) ----------------
__device__ float    g_h[NN * HH];      // x @ W_gcn (L2-resident, 20.5 MB)
__device__ int      g_degi[NN];
__device__ float    g_dinv[NN];
__device__ int      g_off[NN + 1];     // CSR row offsets (by dst)
__device__ int      g_cursor[NN];
__device__ int2     g_edge[EE];        // CSR: (src, bits(dinv[src]))
__device__ int      g_bsum[SBLK];      // scan partials
__device__ int      g_bbase[SBLK];
__device__ float    g_addpool[GG * HH];
__device__ unsigned g_maxpool[GG * HH];
__device__ int      g_counts[GG];

// order-preserving float <-> unsigned encoding for atomicMax
__device__ __forceinline__ unsigned fkey(float f) {
    int i = __float_as_int(f);
    return (unsigned)(i ^ ((i >> 31) | 0x80000000));
}
__device__ __forceinline__ float fdec(unsigned k) {
    int i = (k & 0x80000000u) ? (int)(k ^ 0x80000000u) : (int)(~k);
    return __int_as_float(i);
}

// ---------------- kernels ----------------
__global__ void k_init() {
    int i = blockIdx.x * blockDim.x + threadIdx.x;
    if (i < NN)      g_degi[i] = 0;
    if (i < GG * HH) { g_addpool[i] = 0.f; g_maxpool[i] = 0u; }
    if (i < GG)      g_counts[i] = 0;
}

__global__ void k_deg(const int* __restrict__ ei) {
    int e = blockIdx.x * blockDim.x + threadIdx.x;
    if (e >= EE) return;
    atomicAdd(&g_degi[ei[EE + e]], 1);
}

// ---- 3-phase multi-block exclusive scan of g_degi -> g_off ----
__global__ void k_scanA() {
    __shared__ int s[256];
    int t = threadIdx.x;
    int idx = blockIdx.x * 256 + t;
    int d = (idx < NN) ? g_degi[idx] : 0;
    s[t] = d;
    __syncthreads();
#pragma unroll
    for (int o = 1; o < 256; o <<= 1) {
        int v = (t >= o) ? s[t - o] : 0;
        __syncthreads();
        s[t] += v;
        __syncthreads();
    }
    if (idx < NN) g_off[idx] = s[t] - d;      // block-local exclusive prefix
    if (t == 255) g_bsum[blockIdx.x] = s[255];
}

__global__ void k_scanB() {
    __shared__ int s[256];
    int t = threadIdx.x;
    int d = (t < SBLK) ? g_bsum[t] : 0;
    s[t] = d;
    __syncthreads();
#pragma unroll
    for (int o = 1; o < 256; o <<= 1) {
        int v = (t >= o) ? s[t - o] : 0;
        __syncthreads();
        s[t] += v;
        __syncthreads();
    }
    if (t < SBLK) g_bbase[t] = s[t] - d;      // exclusive base per block
    if (t == SBLK - 1) g_off[NN] = s[t];      // total edge count (== EE)
}

__global__ void k_scanC() {
    int idx = blockIdx.x * 256 + threadIdx.x;
    if (idx >= NN) return;
    int o = g_off[idx] + g_bbase[blockIdx.x];
    g_off[idx] = o;
    g_cursor[idx] = o;
    g_dinv[idx] = rsqrtf((float)g_degi[idx] + 1.0f);
}

__global__ void k_place(const int* __restrict__ ei) {
    int e = blockIdx.x * blockDim.x + threadIdx.x;
    if (e >= EE) return;
    int src = ei[e];
    int dst = ei[EE + e];
    int pos = atomicAdd(&g_cursor[dst], 1);
    g_edge[pos] = make_int2(src, __float_as_int(g_dinv[src]));
}

// h = x @ W. Block tile 64 rows x 128 cols, 256 threads, W fully in smem.
// (Round-2 proven version: 47.5us)
__global__ void k_gemm(const float* __restrict__ x, const float* __restrict__ W) {
    extern __shared__ float sm[];
    float* Ws = sm;                 // 128*128
    float* Xs = sm + DD * HH;       // 16 * 72 (transposed x tile)
    const int XLD = 72;
    int tid = threadIdx.x;
    int row0 = blockIdx.x * 64;

    for (int i = tid; i < (DD * HH) / 4; i += 256)
        ((float4*)Ws)[i] = ((const float4*)W)[i];

    int tx = tid & 31;
    int ty = tid >> 5;
    float acc[8][4];
#pragma unroll
    for (int r = 0; r < 8; r++)
#pragma unroll
        for (int c = 0; c < 4; c++) acc[r][c] = 0.f;

    int lr = tid >> 2, lk = tid & 3;
    for (int kt = 0; kt < DD; kt += 16) {
        __syncthreads();
        float4 xv = *(const float4*)(x + (size_t)(row0 + lr) * DD + kt + lk * 4);
        Xs[(lk * 4 + 0) * XLD + lr] = xv.x;
        Xs[(lk * 4 + 1) * XLD + lr] = xv.y;
        Xs[(lk * 4 + 2) * XLD + lr] = xv.z;
        Xs[(lk * 4 + 3) * XLD + lr] = xv.w;
        __syncthreads();
#pragma unroll
        for (int kk = 0; kk < 16; kk++) {
            float4 wv = *(const float4*)(Ws + (kt + kk) * HH + tx * 4);
            float4 xa = *(const float4*)(Xs + kk * XLD + ty * 8);
            float4 xb = *(const float4*)(Xs + kk * XLD + ty * 8 + 4);
            float xr[8] = {xa.x, xa.y, xa.z, xa.w, xb.x, xb.y, xb.z, xb.w};
#pragma unroll
            for (int r = 0; r < 8; r++) {
                acc[r][0] = fmaf(xr[r], wv.x, acc[r][0]);
                acc[r][1] = fmaf(xr[r], wv.y, acc[r][1]);
                acc[r][2] = fmaf(xr[r], wv.z, acc[r][2]);
                acc[r][3] = fmaf(xr[r], wv.w, acc[r][3]);
            }
        }
    }
#pragma unroll
    for (int r = 0; r < 8; r++) {
        float4 o = make_float4(acc[r][0], acc[r][1], acc[r][2], acc[r][3]);
        *(float4*)(g_h + (size_t)(row0 + ty * 8 + r) * HH + tx * 4) = o;
    }
}

__device__ __forceinline__ void pool_flush(int g, int f, float4 padd, float4 pmax,
                                           int pcnt, int lane) {
    float* p = g_addpool + g * HH + f;
    asm volatile("red.global.add.v4.f32 [%0], {%1, %2, %3, %4};"
                 :: "l"(p), "f"(padd.x), "f"(padd.y), "f"(padd.z), "f"(padd.w)
                 : "memory");
    unsigned* mp = g_maxpool + g * HH + f;
    atomicMax(mp + 0, fkey(pmax.x));
    atomicMax(mp + 1, fkey(pmax.y));
    atomicMax(mp + 2, fkey(pmax.z));
    atomicMax(mp + 3, fkey(pmax.w));
    if (lane == 0) atomicAdd(&g_counts[g], pcnt);
}

// One warp per NPW consecutive nodes: CSR gather-reduce + self loop + bias +
// ReLU + LayerNorm + register-privatized pooling (Round-2 proven structure,
// with packed int2 edge loads).
__global__ void __launch_bounds__(256) k_agg(const int* __restrict__ batch,
                                             const float* __restrict__ bgcn,
                                             const float* __restrict__ gamma,
                                             const float* __restrict__ beta) {
    int warp = blockIdx.x * 8 + (threadIdx.x >> 5);
    int n0 = warp * NPW;
    if (n0 >= NN) return;
    int lane = threadIdx.x & 31;
    int f = lane * 4;

    float4 bb = *(const float4*)(bgcn + f);
    float4 ga = *(const float4*)(gamma + f);
    float4 be = *(const float4*)(beta + f);

    float4 padd = make_float4(0.f, 0.f, 0.f, 0.f);
    float4 pmax = make_float4(-FLT_MAX, -FLT_MAX, -FLT_MAX, -FLT_MAX);
    int pcnt = 0;
    int curg = __ldg(&batch[n0]);

#pragma unroll
    for (int k = 0; k < NPW; k++) {
        int n = n0 + k;
        int g = __ldg(&batch[n]);
        if (g != curg) {
            pool_flush(curg, f, padd, pmax, pcnt, lane);
            padd = make_float4(0.f, 0.f, 0.f, 0.f);
            pmax = make_float4(-FLT_MAX, -FLT_MAX, -FLT_MAX, -FLT_MAX);
            pcnt = 0;
            curg = g;
        }
        int s = __ldg(&g_off[n]);
        int e = __ldg(&g_off[n + 1]);
        float4 acc = make_float4(0.f, 0.f, 0.f, 0.f);
        for (int j = s; j < e; j++) {
            int2 p = __ldg(&g_edge[j]);
            float c = __int_as_float(p.y);
            float4 v = *(const float4*)(g_h + (size_t)p.x * HH + f);
            acc.x = fmaf(c, v.x, acc.x);
            acc.y = fmaf(c, v.y, acc.y);
            acc.z = fmaf(c, v.z, acc.z);
            acc.w = fmaf(c, v.w, acc.w);
        }
        float di = g_dinv[n];
        float4 hv = *(const float4*)(g_h + (size_t)n * HH + f);
        float4 v;
        v.x = fmaxf(fmaf(fmaf(hv.x, di, acc.x), di, bb.x), 0.f);
        v.y = fmaxf(fmaf(fmaf(hv.y, di, acc.y), di, bb.y), 0.f);
        v.z = fmaxf(fmaf(fmaf(hv.z, di, acc.z), di, bb.z), 0.f);
        v.w = fmaxf(fmaf(fmaf(hv.w, di, acc.w), di, bb.w), 0.f);

        float ssum = v.x + v.y + v.z + v.w;
        float qsum = v.x * v.x + v.y * v.y + v.z * v.z + v.w * v.w;
#pragma unroll
        for (int o = 16; o; o >>= 1) {
            ssum += __shfl_xor_sync(0xffffffffu, ssum, o);
            qsum += __shfl_xor_sync(0xffffffffu, qsum, o);
        }
        float mean = ssum * (1.f / 128.f);
        float var  = qsum * (1.f / 128.f) - mean * mean;
        float rstd = rsqrtf(var + 1e-5f);

        float4 y;
        y.x = fmaf((v.x - mean) * rstd, ga.x, be.x);
        y.y = fmaf((v.y - mean) * rstd, ga.y, be.y);
        y.z = fmaf((v.z - mean) * rstd, ga.z, be.z);
        y.w = fmaf((v.w - mean) * rstd, ga.w, be.w);

        padd.x += y.x; padd.y += y.y; padd.z += y.z; padd.w += y.w;
        pmax.x = fmaxf(pmax.x, y.x); pmax.y = fmaxf(pmax.y, y.y);
        pmax.z = fmaxf(pmax.z, y.z); pmax.w = fmaxf(pmax.w, y.w);
        pcnt++;
    }
    pool_flush(curg, f, padd, pmax, pcnt, lane);
}

// One block per graph: build [mean|add|max] then 384->128->64->10 MLP.
__global__ void k_final(const float* __restrict__ W1, const float* __restrict__ b1,
                        const float* __restrict__ W2, const float* __restrict__ b2,
                        const float* __restrict__ W3, const float* __restrict__ b3,
                        float* __restrict__ out) {
    __shared__ float gv[3 * HH];
    __shared__ float l1[HH];
    __shared__ float l2[HH / 2];
    int g = blockIdx.x;
    int t = threadIdx.x;  // 128

    int cnt = g_counts[g];
    float ad = g_addpool[g * HH + t];
    float mean = ad / fmaxf((float)cnt, 1.f);
    float mx = (cnt > 0) ? fdec(g_maxpool[g * HH + t]) : 0.f;
    gv[t] = mean;
    gv[HH + t] = ad;
    gv[2 * HH + t] = mx;
    __syncthreads();

    float acc = __ldg(&b1[t]);
    for (int k = 0; k < 3 * HH; k++)
        acc = fmaf(gv[k], __ldg(&W1[k * HH + t]), acc);
    l1[t] = fmaxf(acc, 0.f);
    __syncthreads();

    if (t < HH / 2) {
        float a2 = __ldg(&b2[t]);
        for (int k = 0; k < HH; k++)
            a2 = fmaf(l1[k], __ldg(&W2[k * (HH / 2) + t]), a2);
        l2[t] = fmaxf(a2, 0.f);
    }
    __syncthreads();

    if (t < OO) {
        float a3 = __ldg(&b3[t]);
        for (int k = 0; k < HH / 2; k++)
            a3 = fmaf(l2[k], __ldg(&W3[k * OO + t]), a3);
        out[g * OO + t] = a3;
    }
}

// ---------------- launch ----------------
extern "C" void kernel_launch(void* const* d_in, const int* in_sizes, int n_in,
                              void* d_out, int out_size) {
    const float* x     = (const float*)d_in[0];
    const int*   ei    = (const int*)d_in[1];
    const int*   batch = (const int*)d_in[2];
    int idx = 3;
    if (n_in > 3 && in_sizes[3] == 1) idx = 4;
    const float* Wg    = (const float*)d_in[idx++];
    const float* bg    = (const float*)d_in[idx++];
    const float* gamma = (const float*)d_in[idx++];
    const float* beta  = (const float*)d_in[idx++];
    const float* W1    = (const float*)d_in[idx++];
    const float* b1    = (const float*)d_in[idx++];
    const float* W2    = (const float*)d_in[idx++];
    const float* b2    = (const float*)d_in[idx++];
    const float* W3    = (const float*)d_in[idx++];
    const float* b3    = (const float*)d_in[idx++];
    float* out = (float*)d_out;

    static cudaStream_t s2 = nullptr;
    static cudaEvent_t ev1 = nullptr, ev2 = nullptr;
    if (!s2) {
        cudaStreamCreateWithFlags(&s2, cudaStreamNonBlocking);
        cudaEventCreateWithFlags(&ev1, cudaEventDisableTiming);
        cudaEventCreateWithFlags(&ev2, cudaEventDisableTiming);
    }

    const int smem = (DD * HH + 16 * 72) * (int)sizeof(float);
    cudaFuncSetAttribute(k_gemm, cudaFuncAttributeMaxDynamicSharedMemorySize, smem);

    // fork: gemm (reads only x, W) runs concurrent with the CSR build chain
    cudaEventRecord(ev1, 0);
    cudaStreamWaitEvent(s2, ev1, 0);
    k_gemm<<<NN / 64, 256, smem, s2>>>(x, Wg);
    cudaEventRecord(ev2, s2);

    k_init<<<(NN + 255) / 256, 256>>>();
    k_deg<<<(EE + 255) / 256, 256>>>(ei);
    k_scanA<<<SBLK, 256>>>();
    k_scanB<<<1, 256>>>();
    k_scanC<<<SBLK, 256>>>();
    k_place<<<(EE + 255) / 256, 256>>>(ei);

    cudaStreamWaitEvent(0, ev2, 0);   // join
    k_agg<<<NN / (NPW * 8), 256>>>(batch, bg, gamma, beta);
    k_final<<<GG, 128>>>(W1, b1, W2, b2, W3, b3, out);
}

// round 5
// speedup vs baseline: 2.1202x; 1.1451x over previous
#include <cuda_runtime.h>
#include <cstdint>
#include <cfloat>

#define NN 40000
#define EE 640000
#define GG 64
#define DD 128
#define HH 128
#define OO 10
#define NPW 4            // nodes per warp in k_agg
#define SBLK 157         // scan blocks: ceil(40000/256)

typedef unsigned long long ull;

// ---------------- scratch (static device globals; no allocations) ----------------
__device__ float    g_h[NN * HH];      // x @ W_gcn (L2-resident, 20.5 MB)
__device__ int      g_degi[NN];
__device__ float    g_dinv[NN];
__device__ int      g_off[NN + 1];     // CSR row offsets (by dst)
__device__ int      g_cursor[NN];
__device__ int2     g_edge[EE];        // CSR: (src, bits(dinv[src]))
__device__ int      g_bsum[SBLK];      // scan partials
__device__ int      g_bbase[SBLK];
__device__ float    g_addpool[GG * HH];
__device__ unsigned g_maxpool[GG * HH];
__device__ int      g_counts[GG];

// order-preserving float <-> unsigned encoding for atomicMax
__device__ __forceinline__ unsigned fkey(float f) {
    int i = __float_as_int(f);
    return (unsigned)(i ^ ((i >> 31) | 0x80000000));
}
__device__ __forceinline__ float fdec(unsigned k) {
    int i = (k & 0x80000000u) ? (int)(k ^ 0x80000000u) : (int)(~k);
    return __int_as_float(i);
}

// packed f32x2 helpers (PTX-only; ptxas never emits FFMA2 from C++)
__device__ __forceinline__ ull pk2(float lo, float hi) {
    ull r; asm("mov.b64 %0, {%1, %2};" : "=l"(r) : "f"(lo), "f"(hi)); return r;
}
__device__ __forceinline__ void upk2(ull v, float& lo, float& hi) {
    asm("mov.b64 {%0, %1}, %2;" : "=f"(lo), "=f"(hi) : "l"(v));
}
__device__ __forceinline__ ull ffma2(ull a, ull b, ull c) {
    ull d; asm("fma.rn.f32x2 %0, %1, %2, %3;" : "=l"(d) : "l"(a), "l"(b), "l"(c));
    return d;
}

// ---------------- kernels ----------------
__global__ void k_init() {
    int i = blockIdx.x * blockDim.x + threadIdx.x;
    if (i < NN)      g_degi[i] = 0;
    if (i < GG * HH) { g_addpool[i] = 0.f; g_maxpool[i] = 0u; }
    if (i < GG)      g_counts[i] = 0;
}

// 4 edges per thread via int4 loads (EE % 4 == 0): 4 atomics in flight.
__global__ void k_deg(const int* __restrict__ ei) {
    int t = blockIdx.x * blockDim.x + threadIdx.x;
    if (t >= EE / 4) return;
    int4 d = ((const int4*)(ei + EE))[t];
    atomicAdd(&g_degi[d.x], 1);
    atomicAdd(&g_degi[d.y], 1);
    atomicAdd(&g_degi[d.z], 1);
    atomicAdd(&g_degi[d.w], 1);
}

// ---- 3-phase multi-block exclusive scan of g_degi -> g_off ----
__global__ void k_scanA() {
    __shared__ int s[256];
    int t = threadIdx.x;
    int idx = blockIdx.x * 256 + t;
    int d = (idx < NN) ? g_degi[idx] : 0;
    s[t] = d;
    __syncthreads();
#pragma unroll
    for (int o = 1; o < 256; o <<= 1) {
        int v = (t >= o) ? s[t - o] : 0;
        __syncthreads();
        s[t] += v;
        __syncthreads();
    }
    if (idx < NN) g_off[idx] = s[t] - d;      // block-local exclusive prefix
    if (t == 255) g_bsum[blockIdx.x] = s[255];
}

__global__ void k_scanB() {
    __shared__ int s[256];
    int t = threadIdx.x;
    int d = (t < SBLK) ? g_bsum[t] : 0;
    s[t] = d;
    __syncthreads();
#pragma unroll
    for (int o = 1; o < 256; o <<= 1) {
        int v = (t >= o) ? s[t - o] : 0;
        __syncthreads();
        s[t] += v;
        __syncthreads();
    }
    if (t < SBLK) g_bbase[t] = s[t] - d;      // exclusive base per block
    if (t == SBLK - 1) g_off[NN] = s[t];
}

__global__ void k_scanC() {
    int idx = blockIdx.x * 256 + threadIdx.x;
    if (idx >= NN) return;
    int o = g_off[idx] + g_bbase[blockIdx.x];
    g_off[idx] = o;
    g_cursor[idx] = o;
    g_dinv[idx] = rsqrtf((float)g_degi[idx] + 1.0f);
}

__global__ void k_place(const int* __restrict__ ei) {
    int e = blockIdx.x * blockDim.x + threadIdx.x;
    if (e >= EE) return;
    int src = ei[e];
    int dst = ei[EE + e];
    int pos = atomicAdd(&g_cursor[dst], 1);
    g_edge[pos] = make_int2(src, __float_as_int(g_dinv[src]));
}

// h = x @ W. 64x128 tile, 256 threads, packed f32x2 FFMA (row-pair accumulators).
__global__ void k_gemm(const float* __restrict__ x, const float* __restrict__ W) {
    extern __shared__ float sm[];
    float* Ws = sm;                 // 128*128
    float* Xs = sm + DD * HH;       // 16 * 72 (transposed x tile)
    const int XLD = 72;
    int tid = threadIdx.x;
    int row0 = blockIdx.x * 64;

    for (int i = tid; i < (DD * HH) / 4; i += 256)
        ((float4*)Ws)[i] = ((const float4*)W)[i];

    int tx = tid & 31;              // cols tx*4 .. tx*4+3
    int ty = tid >> 5;              // rows ty*8 .. ty*8+7 (as 4 pairs)
    ull acc[4][4];                  // [row-pair][col]
#pragma unroll
    for (int rp = 0; rp < 4; rp++)
#pragma unroll
        for (int c = 0; c < 4; c++) acc[rp][c] = 0ULL;

    int lr = tid >> 2, lk = tid & 3;
    for (int kt = 0; kt < DD; kt += 16) {
        __syncthreads();
        float4 xv = *(const float4*)(x + (size_t)(row0 + lr) * DD + kt + lk * 4);
        Xs[(lk * 4 + 0) * XLD + lr] = xv.x;
        Xs[(lk * 4 + 1) * XLD + lr] = xv.y;
        Xs[(lk * 4 + 2) * XLD + lr] = xv.z;
        Xs[(lk * 4 + 3) * XLD + lr] = xv.w;
        __syncthreads();
#pragma unroll
        for (int kk = 0; kk < 16; kk++) {
            float4 wv = *(const float4*)(Ws + (kt + kk) * HH + tx * 4);
            ulonglong2 xa = *(const ulonglong2*)(Xs + kk * XLD + ty * 8);
            ulonglong2 xb = *(const ulonglong2*)(Xs + kk * XLD + ty * 8 + 4);
            ull xp[4] = {xa.x, xa.y, xb.x, xb.y};
            ull w0 = pk2(wv.x, wv.x), w1 = pk2(wv.y, wv.y);
            ull w2 = pk2(wv.z, wv.z), w3 = pk2(wv.w, wv.w);
#pragma unroll
            for (int rp = 0; rp < 4; rp++) {
                acc[rp][0] = ffma2(xp[rp], w0, acc[rp][0]);
                acc[rp][1] = ffma2(xp[rp], w1, acc[rp][1]);
                acc[rp][2] = ffma2(xp[rp], w2, acc[rp][2]);
                acc[rp][3] = ffma2(xp[rp], w3, acc[rp][3]);
            }
        }
    }
#pragma unroll
    for (int rp = 0; rp < 4; rp++) {
        float l0, h0, l1, h1, l2, h2, l3, h3;
        upk2(acc[rp][0], l0, h0);
        upk2(acc[rp][1], l1, h1);
        upk2(acc[rp][2], l2, h2);
        upk2(acc[rp][3], l3, h3);
        size_t r = (size_t)(row0 + ty * 8 + 2 * rp) * HH + tx * 4;
        *(float4*)(g_h + r)      = make_float4(l0, l1, l2, l3);
        *(float4*)(g_h + r + HH) = make_float4(h0, h1, h2, h3);
    }
}

__device__ __forceinline__ void pool_flush(int g, int f, float4 padd, float4 pmax,
                                           int pcnt, int lane) {
    float* p = g_addpool + g * HH + f;
    asm volatile("red.global.add.v4.f32 [%0], {%1, %2, %3, %4};"
                 :: "l"(p), "f"(padd.x), "f"(padd.y), "f"(padd.z), "f"(padd.w)
                 : "memory");
    unsigned* mp = g_maxpool + g * HH + f;
    atomicMax(mp + 0, fkey(pmax.x));
    atomicMax(mp + 1, fkey(pmax.y));
    atomicMax(mp + 2, fkey(pmax.z));
    atomicMax(mp + 3, fkey(pmax.w));
    if (lane == 0) atomicAdd(&g_counts[g], pcnt);
}

// One warp per NPW consecutive nodes: CSR gather-reduce with one-deep edge
// prefetch + self loop + bias + ReLU + LayerNorm + register pooling.
__global__ void __launch_bounds__(256) k_agg(const int* __restrict__ batch,
                                             const float* __restrict__ bgcn,
                                             const float* __restrict__ gamma,
                                             const float* __restrict__ beta) {
    int warp = blockIdx.x * 8 + (threadIdx.x >> 5);
    int n0 = warp * NPW;
    if (n0 >= NN) return;
    int lane = threadIdx.x & 31;
    int f = lane * 4;

    float4 bb = *(const float4*)(bgcn + f);
    float4 ga = *(const float4*)(gamma + f);
    float4 be = *(const float4*)(beta + f);

    float4 padd = make_float4(0.f, 0.f, 0.f, 0.f);
    float4 pmax = make_float4(-FLT_MAX, -FLT_MAX, -FLT_MAX, -FLT_MAX);
    int pcnt = 0;
    int curg = __ldg(&batch[n0]);

#pragma unroll
    for (int k = 0; k < NPW; k++) {
        int n = n0 + k;
        int g = __ldg(&batch[n]);
        if (g != curg) {
            pool_flush(curg, f, padd, pmax, pcnt, lane);
            padd = make_float4(0.f, 0.f, 0.f, 0.f);
            pmax = make_float4(-FLT_MAX, -FLT_MAX, -FLT_MAX, -FLT_MAX);
            pcnt = 0;
            curg = g;
        }
        int s = __ldg(&g_off[n]);
        int e = __ldg(&g_off[n + 1]);
        float4 acc = make_float4(0.f, 0.f, 0.f, 0.f);
        if (s < e) {
            int2 p = __ldg(&g_edge[s]);
            for (int j = s; j < e; j++) {
                // issue next edge load BEFORE consuming current gather:
                int2 pn = (j + 1 < e) ? __ldg(&g_edge[j + 1]) : p;
                float c = __int_as_float(p.y);
                float4 v = *(const float4*)(g_h + (size_t)p.x * HH + f);
                acc.x = fmaf(c, v.x, acc.x);
                acc.y = fmaf(c, v.y, acc.y);
                acc.z = fmaf(c, v.z, acc.z);
                acc.w = fmaf(c, v.w, acc.w);
                p = pn;
            }
        }
        float di = g_dinv[n];
        float4 hv = *(const float4*)(g_h + (size_t)n * HH + f);
        float4 v;
        v.x = fmaxf(fmaf(fmaf(hv.x, di, acc.x), di, bb.x), 0.f);
        v.y = fmaxf(fmaf(fmaf(hv.y, di, acc.y), di, bb.y), 0.f);
        v.z = fmaxf(fmaf(fmaf(hv.z, di, acc.z), di, bb.z), 0.f);
        v.w = fmaxf(fmaf(fmaf(hv.w, di, acc.w), di, bb.w), 0.f);

        float ssum = v.x + v.y + v.z + v.w;
        float qsum = v.x * v.x + v.y * v.y + v.z * v.z + v.w * v.w;
#pragma unroll
        for (int o = 16; o; o >>= 1) {
            ssum += __shfl_xor_sync(0xffffffffu, ssum, o);
            qsum += __shfl_xor_sync(0xffffffffu, qsum, o);
        }
        float mean = ssum * (1.f / 128.f);
        float var  = qsum * (1.f / 128.f) - mean * mean;
        float rstd = rsqrtf(var + 1e-5f);

        float4 y;
        y.x = fmaf((v.x - mean) * rstd, ga.x, be.x);
        y.y = fmaf((v.y - mean) * rstd, ga.y, be.y);
        y.z = fmaf((v.z - mean) * rstd, ga.z, be.z);
        y.w = fmaf((v.w - mean) * rstd, ga.w, be.w);

        padd.x += y.x; padd.y += y.y; padd.z += y.z; padd.w += y.w;
        pmax.x = fmaxf(pmax.x, y.x); pmax.y = fmaxf(pmax.y, y.y);
        pmax.z = fmaxf(pmax.z, y.z); pmax.w = fmaxf(pmax.w, y.w);
        pcnt++;
    }
    pool_flush(curg, f, padd, pmax, pcnt, lane);
}

// One block per graph: build [mean|add|max] then 384->128->64->10 MLP.
__global__ void k_final(const float* __restrict__ W1, const float* __restrict__ b1,
                        const float* __restrict__ W2, const float* __restrict__ b2,
                        const float* __restrict__ W3, const float* __restrict__ b3,
                        float* __restrict__ out) {
    __shared__ float gv[3 * HH];
    __shared__ float l1[HH];
    __shared__ float l2[HH / 2];
    int g = blockIdx.x;
    int t = threadIdx.x;  // 128

    int cnt = g_counts[g];
    float ad = g_addpool[g * HH + t];
    float mean = ad / fmaxf((float)cnt, 1.f);
    float mx = (cnt > 0) ? fdec(g_maxpool[g * HH + t]) : 0.f;
    gv[t] = mean;
    gv[HH + t] = ad;
    gv[2 * HH + t] = mx;
    __syncthreads();

    float acc = __ldg(&b1[t]);
    for (int k = 0; k < 3 * HH; k++)
        acc = fmaf(gv[k], __ldg(&W1[k * HH + t]), acc);
    l1[t] = fmaxf(acc, 0.f);
    __syncthreads();

    if (t < HH / 2) {
        float a2 = __ldg(&b2[t]);
        for (int k = 0; k < HH; k++)
            a2 = fmaf(l1[k], __ldg(&W2[k * (HH / 2) + t]), a2);
        l2[t] = fmaxf(a2, 0.f);
    }
    __syncthreads();

    if (t < OO) {
        float a3 = __ldg(&b3[t]);
        for (int k = 0; k < HH / 2; k++)
            a3 = fmaf(l2[k], __ldg(&W3[k * OO + t]), a3);
        out[g * OO + t] = a3;
    }
}

// ---------------- launch ----------------
extern "C" void kernel_launch(void* const* d_in, const int* in_sizes, int n_in,
                              void* d_out, int out_size) {
    const float* x     = (const float*)d_in[0];
    const int*   ei    = (const int*)d_in[1];
    const int*   batch = (const int*)d_in[2];
    int idx = 3;
    if (n_in > 3 && in_sizes[3] == 1) idx = 4;
    const float* Wg    = (const float*)d_in[idx++];
    const float* bg    = (const float*)d_in[idx++];
    const float* gamma = (const float*)d_in[idx++];
    const float* beta  = (const float*)d_in[idx++];
    const float* W1    = (const float*)d_in[idx++];
    const float* b1    = (const float*)d_in[idx++];
    const float* W2    = (const float*)d_in[idx++];
    const float* b2    = (const float*)d_in[idx++];
    const float* W3    = (const float*)d_in[idx++];
    const float* b3    = (const float*)d_in[idx++];
    float* out = (float*)d_out;

    static cudaStream_t s2 = nullptr;
    static cudaEvent_t ev1 = nullptr, ev2 = nullptr;
    if (!s2) {
        cudaStreamCreateWithFlags(&s2, cudaStreamNonBlocking);
        cudaEventCreateWithFlags(&ev1, cudaEventDisableTiming);
        cudaEventCreateWithFlags(&ev2, cudaEventDisableTiming);
    }

    const int smem = (DD * HH + 16 * 72) * (int)sizeof(float);
    cudaFuncSetAttribute(k_gemm, cudaFuncAttributeMaxDynamicSharedMemorySize, smem);

    // fork: gemm (reads only x, W) runs concurrent with the CSR build chain
    cudaEventRecord(ev1, 0);
    cudaStreamWaitEvent(s2, ev1, 0);
    k_gemm<<<NN / 64, 256, smem, s2>>>(x, Wg);
    cudaEventRecord(ev2, s2);

    k_init<<<(NN + 255) / 256, 256>>>();
    k_deg<<<(EE / 4 + 255) / 256, 256>>>(ei);
    k_scanA<<<SBLK, 256>>>();
    k_scanB<<<1, 256>>>();
    k_scanC<<<SBLK, 256>>>();
    k_place<<<(EE + 255) / 256, 256>>>(ei);

    cudaStreamWaitEvent(0, ev2, 0);   // join
    k_agg<<<NN / (NPW * 8), 256>>>(batch, bg, gamma, beta);
    k_final<<<GG, 128>>>(W1, b1, W2, b2, W3, b3, out);
}

// round 6
// speedup vs baseline: 2.2179x; 1.0461x over previous
#include <cuda_runtime.h>
#include <cstdint>
#include <cfloat>

#define NN 40000
#define EE 640000
#define GG 64
#define DD 128
#define HH 128
#define OO 10
#define NPW 4            // nodes per warp in k_agg
#define SBLK 157         // scan blocks: ceil(40000/256)

typedef unsigned long long ull;

// ---------------- scratch (static device globals; no allocations) ----------------
__device__ float    g_h[NN * HH];      // x @ W_gcn (L2-resident, 20.5 MB)
__device__ int      g_degi[NN];
__device__ float    g_dinv[NN];
__device__ int      g_off[NN + 1];     // CSR row offsets (by dst)
__device__ int      g_cursor[NN];
__device__ int2     g_edge[EE];        // CSR: (src, bits(dinv[src]))
__device__ int      g_bsum[SBLK];      // scan partials
__device__ int      g_bbase[SBLK];
__device__ float    g_addpool[GG * HH];
__device__ unsigned g_maxpool[GG * HH];
__device__ int      g_counts[GG];

// order-preserving float <-> unsigned encoding for atomicMax
__device__ __forceinline__ unsigned fkey(float f) {
    int i = __float_as_int(f);
    return (unsigned)(i ^ ((i >> 31) | 0x80000000));
}
__device__ __forceinline__ float fdec(unsigned k) {
    int i = (k & 0x80000000u) ? (int)(k ^ 0x80000000u) : (int)(~k);
    return __int_as_float(i);
}

// packed f32x2 helpers (PTX-only; ptxas never emits FFMA2 from C++)
__device__ __forceinline__ ull pk2(float lo, float hi) {
    ull r; asm("mov.b64 %0, {%1, %2};" : "=l"(r) : "f"(lo), "f"(hi)); return r;
}
__device__ __forceinline__ void upk2(ull v, float& lo, float& hi) {
    asm("mov.b64 {%0, %1}, %2;" : "=f"(lo), "=f"(hi) : "l"(v));
}
__device__ __forceinline__ ull ffma2(ull a, ull b, ull c) {
    ull d; asm("fma.rn.f32x2 %0, %1, %2, %3;" : "=l"(d) : "l"(a), "l"(b), "l"(c));
    return d;
}

// ---------------- kernels ----------------
__global__ void k_init() {
    int i = blockIdx.x * blockDim.x + threadIdx.x;
    if (i < NN)      g_degi[i] = 0;
    if (i < GG * HH) { g_addpool[i] = 0.f; g_maxpool[i] = 0u; }
    if (i < GG)      g_counts[i] = 0;
}

// 4 edges per thread via int4 loads (EE % 4 == 0): 4 atomics in flight.
__global__ void k_deg(const int* __restrict__ ei) {
    int t = blockIdx.x * blockDim.x + threadIdx.x;
    if (t >= EE / 4) return;
    int4 d = ((const int4*)(ei + EE))[t];
    atomicAdd(&g_degi[d.x], 1);
    atomicAdd(&g_degi[d.y], 1);
    atomicAdd(&g_degi[d.z], 1);
    atomicAdd(&g_degi[d.w], 1);
}

// ---- 3-phase multi-block exclusive scan of g_degi -> g_off ----
__global__ void k_scanA() {
    __shared__ int s[256];
    int t = threadIdx.x;
    int idx = blockIdx.x * 256 + t;
    int d = (idx < NN) ? g_degi[idx] : 0;
    s[t] = d;
    __syncthreads();
#pragma unroll
    for (int o = 1; o < 256; o <<= 1) {
        int v = (t >= o) ? s[t - o] : 0;
        __syncthreads();
        s[t] += v;
        __syncthreads();
    }
    if (idx < NN) g_off[idx] = s[t] - d;      // block-local exclusive prefix
    if (t == 255) g_bsum[blockIdx.x] = s[255];
}

__global__ void k_scanB() {
    __shared__ int s[256];
    int t = threadIdx.x;
    int d = (t < SBLK) ? g_bsum[t] : 0;
    s[t] = d;
    __syncthreads();
#pragma unroll
    for (int o = 1; o < 256; o <<= 1) {
        int v = (t >= o) ? s[t - o] : 0;
        __syncthreads();
        s[t] += v;
        __syncthreads();
    }
    if (t < SBLK) g_bbase[t] = s[t] - d;      // exclusive base per block
    if (t == SBLK - 1) g_off[NN] = s[t];
}

__global__ void k_scanC() {
    int idx = blockIdx.x * 256 + threadIdx.x;
    if (idx >= NN) return;
    int o = g_off[idx] + g_bbase[blockIdx.x];
    g_off[idx] = o;
    g_cursor[idx] = o;
    g_dinv[idx] = rsqrtf((float)g_degi[idx] + 1.0f);
}

// 4 edges per thread: 4 independent cursor atomics + 4 stores in flight.
__global__ void k_place(const int* __restrict__ ei) {
    int t = blockIdx.x * blockDim.x + threadIdx.x;
    if (t >= EE / 4) return;
    int4 s4 = ((const int4*)ei)[t];             // 4 src
    int4 d4 = ((const int4*)(ei + EE))[t];      // 4 dst
    int p0 = atomicAdd(&g_cursor[d4.x], 1);
    int p1 = atomicAdd(&g_cursor[d4.y], 1);
    int p2 = atomicAdd(&g_cursor[d4.z], 1);
    int p3 = atomicAdd(&g_cursor[d4.w], 1);
    float c0 = g_dinv[s4.x], c1 = g_dinv[s4.y];
    float c2 = g_dinv[s4.z], c3 = g_dinv[s4.w];
    g_edge[p0] = make_int2(s4.x, __float_as_int(c0));
    g_edge[p1] = make_int2(s4.y, __float_as_int(c1));
    g_edge[p2] = make_int2(s4.z, __float_as_int(c2));
    g_edge[p3] = make_int2(s4.w, __float_as_int(c3));
}

// h = x @ W. 64x128 tile, 256 threads, packed f32x2 FFMA (row-pair accumulators).
__global__ void k_gemm(const float* __restrict__ x, const float* __restrict__ W) {
    extern __shared__ float sm[];
    float* Ws = sm;                 // 128*128
    float* Xs = sm + DD * HH;       // 16 * 72 (transposed x tile)
    const int XLD = 72;
    int tid = threadIdx.x;
    int row0 = blockIdx.x * 64;

    for (int i = tid; i < (DD * HH) / 4; i += 256)
        ((float4*)Ws)[i] = ((const float4*)W)[i];

    int tx = tid & 31;              // cols tx*4 .. tx*4+3
    int ty = tid >> 5;              // rows ty*8 .. ty*8+7 (as 4 pairs)
    ull acc[4][4];                  // [row-pair][col]
#pragma unroll
    for (int rp = 0; rp < 4; rp++)
#pragma unroll
        for (int c = 0; c < 4; c++) acc[rp][c] = 0ULL;

    int lr = tid >> 2, lk = tid & 3;
    for (int kt = 0; kt < DD; kt += 16) {
        __syncthreads();
        float4 xv = *(const float4*)(x + (size_t)(row0 + lr) * DD + kt + lk * 4);
        Xs[(lk * 4 + 0) * XLD + lr] = xv.x;
        Xs[(lk * 4 + 1) * XLD + lr] = xv.y;
        Xs[(lk * 4 + 2) * XLD + lr] = xv.z;
        Xs[(lk * 4 + 3) * XLD + lr] = xv.w;
        __syncthreads();
#pragma unroll
        for (int kk = 0; kk < 16; kk++) {
            float4 wv = *(const float4*)(Ws + (kt + kk) * HH + tx * 4);
            ulonglong2 xa = *(const ulonglong2*)(Xs + kk * XLD + ty * 8);
            ulonglong2 xb = *(const ulonglong2*)(Xs + kk * XLD + ty * 8 + 4);
            ull xp[4] = {xa.x, xa.y, xb.x, xb.y};
            ull w0 = pk2(wv.x, wv.x), w1 = pk2(wv.y, wv.y);
            ull w2 = pk2(wv.z, wv.z), w3 = pk2(wv.w, wv.w);
#pragma unroll
            for (int rp = 0; rp < 4; rp++) {
                acc[rp][0] = ffma2(xp[rp], w0, acc[rp][0]);
                acc[rp][1] = ffma2(xp[rp], w1, acc[rp][1]);
                acc[rp][2] = ffma2(xp[rp], w2, acc[rp][2]);
                acc[rp][3] = ffma2(xp[rp], w3, acc[rp][3]);
            }
        }
    }
#pragma unroll
    for (int rp = 0; rp < 4; rp++) {
        float l0, h0, l1, h1, l2, h2, l3, h3;
        upk2(acc[rp][0], l0, h0);
        upk2(acc[rp][1], l1, h1);
        upk2(acc[rp][2], l2, h2);
        upk2(acc[rp][3], l3, h3);
        size_t r = (size_t)(row0 + ty * 8 + 2 * rp) * HH + tx * 4;
        *(float4*)(g_h + r)      = make_float4(l0, l1, l2, l3);
        *(float4*)(g_h + r + HH) = make_float4(h0, h1, h2, h3);
    }
}

__device__ __forceinline__ void pool_flush(int g, int f, float4 padd, float4 pmax,
                                           int pcnt, int lane) {
    float* p = g_addpool + g * HH + f;
    asm volatile("red.global.add.v4.f32 [%0], {%1, %2, %3, %4};"
                 :: "l"(p), "f"(padd.x), "f"(padd.y), "f"(padd.z), "f"(padd.w)
                 : "memory");
    unsigned* mp = g_maxpool + g * HH + f;
    atomicMax(mp + 0, fkey(pmax.x));
    atomicMax(mp + 1, fkey(pmax.y));
    atomicMax(mp + 2, fkey(pmax.z));
    atomicMax(mp + 3, fkey(pmax.w));
    if (lane == 0) atomicAdd(&g_counts[g], pcnt);
}

// One warp per NPW consecutive nodes: 2-wide CSR gather-reduce (dual acc) +
// self loop + bias + ReLU + LayerNorm + register pooling.
__global__ void __launch_bounds__(256) k_agg(const int* __restrict__ batch,
                                             const float* __restrict__ bgcn,
                                             const float* __restrict__ gamma,
                                             const float* __restrict__ beta) {
    int warp = blockIdx.x * 8 + (threadIdx.x >> 5);
    int n0 = warp * NPW;
    if (n0 >= NN) return;
    int lane = threadIdx.x & 31;
    int f = lane * 4;

    float4 bb = *(const float4*)(bgcn + f);
    float4 ga = *(const float4*)(gamma + f);
    float4 be = *(const float4*)(beta + f);

    float4 padd = make_float4(0.f, 0.f, 0.f, 0.f);
    float4 pmax = make_float4(-FLT_MAX, -FLT_MAX, -FLT_MAX, -FLT_MAX);
    int pcnt = 0;
    int curg = __ldg(&batch[n0]);

#pragma unroll
    for (int k = 0; k < NPW; k++) {
        int n = n0 + k;
        int g = __ldg(&batch[n]);
        if (g != curg) {
            pool_flush(curg, f, padd, pmax, pcnt, lane);
            padd = make_float4(0.f, 0.f, 0.f, 0.f);
            pmax = make_float4(-FLT_MAX, -FLT_MAX, -FLT_MAX, -FLT_MAX);
            pcnt = 0;
            curg = g;
        }
        int s = __ldg(&g_off[n]);
        int e = __ldg(&g_off[n + 1]);
        float4 a0 = make_float4(0.f, 0.f, 0.f, 0.f);
        float4 a1 = make_float4(0.f, 0.f, 0.f, 0.f);
        int j = s;
        if ((j & 1) && j < e) {             // align to int4 boundary
            int2 p = __ldg(&g_edge[j]);
            float c = __int_as_float(p.y);
            float4 v = *(const float4*)(g_h + (size_t)p.x * HH + f);
            a0.x = fmaf(c, v.x, a0.x); a0.y = fmaf(c, v.y, a0.y);
            a0.z = fmaf(c, v.z, a0.z); a0.w = fmaf(c, v.w, a0.w);
            j++;
        }
        for (; j + 2 <= e; j += 2) {        // 2 independent gathers in flight
            int4 q = *(const int4*)(g_edge + j);   // two edges, one broadcast ld
            float4 v0 = *(const float4*)(g_h + (size_t)q.x * HH + f);
            float4 v1 = *(const float4*)(g_h + (size_t)q.z * HH + f);
            float c0 = __int_as_float(q.y), c1 = __int_as_float(q.w);
            a0.x = fmaf(c0, v0.x, a0.x); a0.y = fmaf(c0, v0.y, a0.y);
            a0.z = fmaf(c0, v0.z, a0.z); a0.w = fmaf(c0, v0.w, a0.w);
            a1.x = fmaf(c1, v1.x, a1.x); a1.y = fmaf(c1, v1.y, a1.y);
            a1.z = fmaf(c1, v1.z, a1.z); a1.w = fmaf(c1, v1.w, a1.w);
        }
        if (j < e) {                        // tail (at most 1)
            int2 p = __ldg(&g_edge[j]);
            float c = __int_as_float(p.y);
            float4 v = *(const float4*)(g_h + (size_t)p.x * HH + f);
            a0.x = fmaf(c, v.x, a0.x); a0.y = fmaf(c, v.y, a0.y);
            a0.z = fmaf(c, v.z, a0.z); a0.w = fmaf(c, v.w, a0.w);
        }
        float4 acc = make_float4(a0.x + a1.x, a0.y + a1.y,
                                 a0.z + a1.z, a0.w + a1.w);

        float di = g_dinv[n];
        float4 hv = *(const float4*)(g_h + (size_t)n * HH + f);
        float4 v;
        v.x = fmaxf(fmaf(fmaf(hv.x, di, acc.x), di, bb.x), 0.f);
        v.y = fmaxf(fmaf(fmaf(hv.y, di, acc.y), di, bb.y), 0.f);
        v.z = fmaxf(fmaf(fmaf(hv.z, di, acc.z), di, bb.z), 0.f);
        v.w = fmaxf(fmaf(fmaf(hv.w, di, acc.w), di, bb.w), 0.f);

        float ssum = v.x + v.y + v.z + v.w;
        float qsum = v.x * v.x + v.y * v.y + v.z * v.z + v.w * v.w;
#pragma unroll
        for (int o = 16; o; o >>= 1) {
            ssum += __shfl_xor_sync(0xffffffffu, ssum, o);
            qsum += __shfl_xor_sync(0xffffffffu, qsum, o);
        }
        float mean = ssum * (1.f / 128.f);
        float var  = qsum * (1.f / 128.f) - mean * mean;
        float rstd = rsqrtf(var + 1e-5f);

        float4 y;
        y.x = fmaf((v.x - mean) * rstd, ga.x, be.x);
        y.y = fmaf((v.y - mean) * rstd, ga.y, be.y);
        y.z = fmaf((v.z - mean) * rstd, ga.z, be.z);
        y.w = fmaf((v.w - mean) * rstd, ga.w, be.w);

        padd.x += y.x; padd.y += y.y; padd.z += y.z; padd.w += y.w;
        pmax.x = fmaxf(pmax.x, y.x); pmax.y = fmaxf(pmax.y, y.y);
        pmax.z = fmaxf(pmax.z, y.z); pmax.w = fmaxf(pmax.w, y.w);
        pcnt++;
    }
    pool_flush(curg, f, padd, pmax, pcnt, lane);
}

// One block per graph: build [mean|add|max] then 384->128->64->10 MLP.
__global__ void k_final(const float* __restrict__ W1, const float* __restrict__ b1,
                        const float* __restrict__ W2, const float* __restrict__ b2,
                        const float* __restrict__ W3, const float* __restrict__ b3,
                        float* __restrict__ out) {
    __shared__ float gv[3 * HH];
    __shared__ float l1[HH];
    __shared__ float l2[HH / 2];
    int g = blockIdx.x;
    int t = threadIdx.x;  // 128

    int cnt = g_counts[g];
    float ad = g_addpool[g * HH + t];
    float mean = ad / fmaxf((float)cnt, 1.f);
    float mx = (cnt > 0) ? fdec(g_maxpool[g * HH + t]) : 0.f;
    gv[t] = mean;
    gv[HH + t] = ad;
    gv[2 * HH + t] = mx;
    __syncthreads();

    float acc = __ldg(&b1[t]);
    for (int k = 0; k < 3 * HH; k++)
        acc = fmaf(gv[k], __ldg(&W1[k * HH + t]), acc);
    l1[t] = fmaxf(acc, 0.f);
    __syncthreads();

    if (t < HH / 2) {
        float a2 = __ldg(&b2[t]);
        for (int k = 0; k < HH; k++)
            a2 = fmaf(l1[k], __ldg(&W2[k * (HH / 2) + t]), a2);
        l2[t] = fmaxf(a2, 0.f);
    }
    __syncthreads();

    if (t < OO) {
        float a3 = __ldg(&b3[t]);
        for (int k = 0; k < HH / 2; k++)
            a3 = fmaf(l2[k], __ldg(&W3[k * OO + t]), a3);
        out[g * OO + t] = a3;
    }
}

// ---------------- launch ----------------
extern "C" void kernel_launch(void* const* d_in, const int* in_sizes, int n_in,
                              void* d_out, int out_size) {
    const float* x     = (const float*)d_in[0];
    const int*   ei    = (const int*)d_in[1];
    const int*   batch = (const int*)d_in[2];
    int idx = 3;
    if (n_in > 3 && in_sizes[3] == 1) idx = 4;
    const float* Wg    = (const float*)d_in[idx++];
    const float* bg    = (const float*)d_in[idx++];
    const float* gamma = (const float*)d_in[idx++];
    const float* beta  = (const float*)d_in[idx++];
    const float* W1    = (const float*)d_in[idx++];
    const float* b1    = (const float*)d_in[idx++];
    const float* W2    = (const float*)d_in[idx++];
    const float* b2    = (const float*)d_in[idx++];
    const float* W3    = (const float*)d_in[idx++];
    const float* b3    = (const float*)d_in[idx++];
    float* out = (float*)d_out;

    static cudaStream_t s2 = nullptr;
    static cudaEvent_t ev1 = nullptr, ev2 = nullptr;
    if (!s2) {
        cudaStreamCreateWithFlags(&s2, cudaStreamNonBlocking);
        cudaEventCreateWithFlags(&ev1, cudaEventDisableTiming);
        cudaEventCreateWithFlags(&ev2, cudaEventDisableTiming);
    }

    const int smem = (DD * HH + 16 * 72) * (int)sizeof(float);
    cudaFuncSetAttribute(k_gemm, cudaFuncAttributeMaxDynamicSharedMemorySize, smem);

    // fork: gemm (reads only x, W) runs concurrent with the CSR build chain
    cudaEventRecord(ev1, 0);
    cudaStreamWaitEvent(s2, ev1, 0);
    k_gemm<<<NN / 64, 256, smem, s2>>>(x, Wg);
    cudaEventRecord(ev2, s2);

    k_init<<<(NN + 255) / 256, 256>>>();
    k_deg<<<(EE / 4 + 255) / 256, 256>>>(ei);
    k_scanA<<<SBLK, 256>>>();
    k_scanB<<<1, 256>>>();
    k_scanC<<<SBLK, 256>>>();
    k_place<<<(EE / 4 + 255) / 256, 256>>>(ei);

    cudaStreamWaitEvent(0, ev2, 0);   // join
    k_agg<<<NN / (NPW * 8), 256>>>(batch, bg, gamma, beta);
    k_final<<<GG, 128>>>(W1, b1, W2, b2, W3, b3, out);
}